// round 15
// baseline (speedup 1.0000x reference)
#include <cuda_runtime.h>
#include <cuda_bf16.h>
#include <cstdint>
#include <math.h>

// ---------------------------------------------------------------------------
// BertAdapter, 4-kernel split:
//   prep_t : transpose+bf16 weights (smem tiles)
//   ln     : x -> LN(x) bf16 (g_xn, L2-resident)   one pass, streaming
//   g1     : xn@Wd + gelu -> inter      pure cp.async GEMM, 2 CTAs/SM
//   g2     : inter@Wu + bias + residual -> out. Chunked-N: A tile resident in
//            smem, 16 Wu chunks of 64n; epilogue DRAM traffic spread.
// mma.sync m16n8k16 bf16 (plain sm_103 target: no tcgen05).
// ---------------------------------------------------------------------------

#define TOKENS   32768
#define HIDDEN   1024
#define ADAPTER  256

__device__ __nv_bfloat16 g_wdT[HIDDEN * ADAPTER];   // wdT[n*1024 + k] = wd[k][n]
__device__ __nv_bfloat16 g_wuT[ADAPTER * HIDDEN];   // wuT[n*256  + k] = wu[k][n]
__device__ __nv_bfloat16 g_xn[TOKENS * HIDDEN];     // LN(x) bf16, 64MB
__device__ __nv_bfloat16 g_inter[TOKENS * ADAPTER]; // 16MB

// ---------------- helpers ----------------
static __device__ __forceinline__ uint32_t smem_u32(const void* p) {
    uint32_t a;
    asm("{ .reg .u64 t; cvta.to.shared.u64 t, %1; cvt.u32.u64 %0, t; }"
        : "=r"(a) : "l"(p));
    return a;
}
static __device__ __forceinline__ uint32_t sw128(uint32_t o) {
    return o ^ ((o >> 3) & 0x70);
}

#define LDMATRIX_X4(r0, r1, r2, r3, addr)                                      \
    asm volatile("ldmatrix.sync.aligned.m8n8.x4.shared.b16 {%0,%1,%2,%3}, [%4];" \
                 : "=r"(r0), "=r"(r1), "=r"(r2), "=r"(r3) : "r"(addr))

#define MMA_BF16(d, a, bb0, bb1)                                               \
    asm volatile(                                                              \
        "mma.sync.aligned.m16n8k16.row.col.f32.bf16.bf16.f32 "                 \
        "{%0,%1,%2,%3}, {%4,%5,%6,%7}, {%8,%9}, {%0,%1,%2,%3};"                \
        : "+f"((d)[0]), "+f"((d)[1]), "+f"((d)[2]), "+f"((d)[3])               \
        : "r"((a)[0]), "r"((a)[1]), "r"((a)[2]), "r"((a)[3]),                  \
          "r"(bb0), "r"(bb1))

#define CP_ASYNC16(dst, src)                                                   \
    asm volatile("cp.async.cg.shared.global [%0], [%1], 16;"                   \
                 :: "r"(dst), "l"(src))
#define CP_COMMIT() asm volatile("cp.async.commit_group;" ::: "memory")
#define CP_WAIT0()  asm volatile("cp.async.wait_group 0;" ::: "memory")

static __device__ __forceinline__ float gelu_new_f(float x) {
    float x3 = x * x * x;
    float t = tanhf(0.7978845608028654f * (x + 0.044715f * x3));
    return 0.5f * x * (1.0f + t);
}

struct Frag64 { float a[2][8][4]; };   // warp tile 32m x 64n
struct Frag32 { float a[2][4][4]; };   // warp tile 32m x 32n

static __device__ __forceinline__ void tile_compute64(uint32_t ab, uint32_t bb,
                                                      int lid, int wm, int wn,
                                                      Frag64& f) {
#pragma unroll
    for (int kk = 0; kk < 4; kk++) {
        uint32_t a[2][4];
#pragma unroll
        for (int mt = 0; mt < 2; mt++) {
            uint32_t off = (uint32_t)(wm + mt * 16 + (lid & 15)) * 128u +
                           (uint32_t)(kk * 32 + ((lid >> 4) << 4));
            LDMATRIX_X4(a[mt][0], a[mt][1], a[mt][2], a[mt][3], ab + sw128(off));
        }
        uint32_t b[4][4];
#pragma unroll
        for (int g = 0; g < 4; g++) {
            uint32_t row = (uint32_t)(wn + g * 16 + (lid & 7) + ((lid >> 4) << 3));
            uint32_t off = row * 128u +
                           (uint32_t)(kk * 32 + (((lid >> 3) & 1) << 4));
            LDMATRIX_X4(b[g][0], b[g][1], b[g][2], b[g][3], bb + sw128(off));
        }
#pragma unroll
        for (int mt = 0; mt < 2; mt++)
#pragma unroll
            for (int nt = 0; nt < 8; nt++) {
                int g = nt >> 1;
                if ((nt & 1) == 0) MMA_BF16(f.a[mt][nt], a[mt], b[g][0], b[g][1]);
                else               MMA_BF16(f.a[mt][nt], a[mt], b[g][2], b[g][3]);
            }
    }
}

static __device__ __forceinline__ void tile_compute32(uint32_t ab, uint32_t bb,
                                                      int lid, int wm, int wn,
                                                      Frag32& f) {
#pragma unroll
    for (int kk = 0; kk < 4; kk++) {
        uint32_t a[2][4];
#pragma unroll
        for (int mt = 0; mt < 2; mt++) {
            uint32_t off = (uint32_t)(wm + mt * 16 + (lid & 15)) * 128u +
                           (uint32_t)(kk * 32 + ((lid >> 4) << 4));
            LDMATRIX_X4(a[mt][0], a[mt][1], a[mt][2], a[mt][3], ab + sw128(off));
        }
        uint32_t b[2][4];
#pragma unroll
        for (int g = 0; g < 2; g++) {
            uint32_t row = (uint32_t)(wn + g * 16 + (lid & 7) + ((lid >> 4) << 3));
            uint32_t off = row * 128u +
                           (uint32_t)(kk * 32 + (((lid >> 3) & 1) << 4));
            LDMATRIX_X4(b[g][0], b[g][1], b[g][2], b[g][3], bb + sw128(off));
        }
#pragma unroll
        for (int mt = 0; mt < 2; mt++)
#pragma unroll
            for (int nt = 0; nt < 4; nt++) {
                int g = nt >> 1;
                if ((nt & 1) == 0) MMA_BF16(f.a[mt][nt], a[mt], b[g][0], b[g][1]);
                else               MMA_BF16(f.a[mt][nt], a[mt], b[g][2], b[g][3]);
            }
    }
}

// ---------------- prep: smem-tile transpose + bf16 convert ----------------
__global__ void __launch_bounds__(256) prep_t(const float* __restrict__ wd,
                                              const float* __restrict__ wu) {
    __shared__ float t[32][33];
    int b = blockIdx.x;
    int r = threadIdx.x >> 5, c = threadIdx.x & 31;
    if (b < 256) {          // wd [1024k][256n] -> wdT [256n][1024k]
        int k0 = (b >> 3) * 32, n0 = (b & 7) * 32;
#pragma unroll
        for (int i = 0; i < 4; i++)
            t[r + i * 8][c] = wd[(size_t)(k0 + r + i * 8) * 256 + n0 + c];
        __syncthreads();
#pragma unroll
        for (int i = 0; i < 4; i++)
            g_wdT[(size_t)(n0 + r + i * 8) * 1024 + k0 + c] =
                __float2bfloat16(t[c][r + i * 8]);
    } else {                // wu [256k][1024n] -> wuT [1024n][256k]
        b -= 256;
        int k0 = (b & 7) * 32, n0 = (b >> 3) * 32;
#pragma unroll
        for (int i = 0; i < 4; i++)
            t[r + i * 8][c] = wu[(size_t)(k0 + r + i * 8) * 1024 + n0 + c];
        __syncthreads();
#pragma unroll
        for (int i = 0; i < 4; i++)
            g_wuT[(size_t)(n0 + r + i * 8) * 256 + k0 + c] =
                __float2bfloat16(t[c][r + i * 8]);
    }
}

// ---------------- ln: x -> LN(x) bf16, one pass, streaming ----------------
__global__ void __launch_bounds__(256) ln_kernel(const float* __restrict__ x,
                                                 const float* __restrict__ lnw,
                                                 const float* __restrict__ lnb) {
    int row = blockIdx.x * 8 + (threadIdx.x >> 5);
    int lid = threadIdx.x & 31;
    const float4* p = (const float4*)x + (size_t)row * 256;
    const float4* w4 = (const float4*)lnw;
    const float4* b4 = (const float4*)lnb;

    float4 v[8];
    float s = 0.f, ss = 0.f;
#pragma unroll
    for (int i = 0; i < 8; i++) {
        v[i] = p[lid + i * 32];
        s  += v[i].x + v[i].y + v[i].z + v[i].w;
        ss += v[i].x * v[i].x + v[i].y * v[i].y +
              v[i].z * v[i].z + v[i].w * v[i].w;
    }
#pragma unroll
    for (int o = 16; o; o >>= 1) {
        s  += __shfl_xor_sync(0xFFFFFFFFu, s, o);
        ss += __shfl_xor_sync(0xFFFFFFFFu, ss, o);
    }
    float mu = s * (1.0f / 1024.0f);
    float rs = rsqrtf(ss * (1.0f / 1024.0f) - mu * mu + 1e-5f);

    uint2* dst = (uint2*)(g_xn + (size_t)row * 1024);
#pragma unroll
    for (int i = 0; i < 8; i++) {
        int k4 = lid + i * 32;
        float4 w = w4[k4], b = b4[k4];
        __nv_bfloat162 p0 = __floats2bfloat162_rn((v[i].x - mu) * rs * w.x + b.x,
                                                  (v[i].y - mu) * rs * w.y + b.y);
        __nv_bfloat162 p1 = __floats2bfloat162_rn((v[i].z - mu) * rs * w.z + b.z,
                                                  (v[i].w - mu) * rs * w.w + b.w);
        uint2 val;
        val.x = *(uint32_t*)&p0;
        val.y = *(uint32_t*)&p1;
        __stcg(dst + k4, val);     // L2-resident, bypass L1
    }
}

// g1 smem (1024-aligned): A0@0, A1@16384, B0@32768, B1@49152
#define G_A0 0u
#define G_A1 16384u
#define G_B0 32768u
#define G_B1 49152u
#define G_SMEM (65536 + 1024)

// ---------------- g1: xn@Wd + gelu -> inter (pure GEMM) -------------------
__global__ void __launch_bounds__(256, 2)
g1_kernel(const float* __restrict__ bdown) {
    extern __shared__ char smem_raw[];
    const int tid = threadIdx.x, wid = tid >> 5, lid = tid & 31;
    const int m0 = blockIdx.x * 128;
    const int n0 = blockIdx.y * 128;

    uint32_t sb0 = smem_u32(smem_raw);
    uint32_t pad = (1024u - (sb0 & 1023u)) & 1023u;
    uint32_t sb = sb0 + pad;

    const uint4* xn4  = (const uint4*)g_xn;     // 128 uint4 per 1024-bf16 row
    const uint4* wdT4 = (const uint4*)g_wdT;    // 128 uint4 per row

    auto loadAB = [&](int kt, uint32_t abuf, uint32_t bbuf) {   // 16KB each
#pragma unroll
        for (int i = 0; i < 4; i++) {
            int idx = tid + i * 256;
            int r = idx >> 3, u = idx & 7;
            uint32_t so = sw128((uint32_t)r * 128u + (uint32_t)u * 16u);
            CP_ASYNC16(abuf + so, xn4  + (size_t)(m0 + r) * 128 + kt * 8 + u);
            CP_ASYNC16(bbuf + so, wdT4 + (size_t)(n0 + r) * 128 + kt * 8 + u);
        }
        CP_COMMIT();
    };

    Frag64 f1;
#pragma unroll
    for (int mt = 0; mt < 2; mt++)
#pragma unroll
        for (int nt = 0; nt < 8; nt++)
#pragma unroll
            for (int j = 0; j < 4; j++) f1.a[mt][nt][j] = 0.f;

    const int wm = (wid & 3) * 32, wn = (wid >> 2) * 64;

    loadAB(0, sb + G_A0, sb + G_B0);
    CP_WAIT0();
    __syncthreads();

#pragma unroll 1
    for (int kt = 0; kt < 16; kt++) {
        int buf = kt & 1;
        if (kt + 1 < 16)
            loadAB(kt + 1, sb + (buf ? G_A0 : G_A1), sb + (buf ? G_B0 : G_B1));
        tile_compute64(sb + (buf ? G_A1 : G_A0),
                       sb + (buf ? G_B1 : G_B0), lid, wm, wn, f1);
        CP_WAIT0();
        __syncthreads();
    }

    // gelu + bias -> inter (bf16)
    uint32_t* dst = (uint32_t*)g_inter;
#pragma unroll
    for (int mt = 0; mt < 2; mt++)
#pragma unroll
        for (int nt = 0; nt < 8; nt++) {
            int col = n0 + wn + nt * 8 + (lid & 3) * 2;
            int row = m0 + wm + mt * 16 + (lid >> 2);
            float b0 = bdown[col], b1 = bdown[col + 1];
            float* c = f1.a[mt][nt];
            __nv_bfloat162 p0 = __floats2bfloat162_rn(gelu_new_f(c[0] + b0),
                                                      gelu_new_f(c[1] + b1));
            __nv_bfloat162 p1 = __floats2bfloat162_rn(gelu_new_f(c[2] + b0),
                                                      gelu_new_f(c[3] + b1));
            dst[(size_t)row * 128 + (col >> 1)]       = *(uint32_t*)&p0;
            dst[(size_t)(row + 8) * 128 + (col >> 1)] = *(uint32_t*)&p1;
        }
}

// g2 smem (1024-aligned): A panels 4x16KB @0; Wu buf 4x8KB @65536. 96KB.
#define V_A 0u
#define V_B 65536u
#define V_SMEM (98304 + 1024)

// ---------------- g2: inter@Wu + bias + residual -> out (chunked-N) -------
__global__ void __launch_bounds__(256, 2)
g2_kernel(const float* __restrict__ x, const float* __restrict__ bup,
          float* __restrict__ out) {
    extern __shared__ char smem_raw[];
    const int tid = threadIdx.x, wid = tid >> 5, lid = tid & 31;
    const int m0 = blockIdx.x * 128;

    uint32_t sb0 = smem_u32(smem_raw);
    uint32_t pad = (1024u - (sb0 & 1023u)) & 1023u;
    uint32_t sb = sb0 + pad;

    const uint4* a4  = (const uint4*)g_inter;   // 32 uint4 per 256-bf16 row
    const uint4* wt4 = (const uint4*)g_wuT;     // 32 uint4 per row

    // load resident A tile: 128 rows x 256k = 64KB into 4 k-panels
#pragma unroll
    for (int i = 0; i < 16; i++) {
        int idx = tid + i * 256;                // 0..4095 16B units
        int r = idx >> 5, u = idx & 31;         // row, unit
        int q = u >> 3, u8 = u & 7;             // k-panel, unit in panel
        uint32_t dst = sb + V_A + (uint32_t)q * 16384u +
                       sw128((uint32_t)r * 128u + (uint32_t)u8 * 16u);
        CP_ASYNC16(dst, a4 + (size_t)(m0 + r) * 32 + u);
    }
    CP_COMMIT();

    auto loadWu = [&](int nc) {   // 64 n-rows x 256k = 32KB into 4 k-panels
#pragma unroll
        for (int i = 0; i < 8; i++) {
            int idx = tid + i * 256;            // 0..2047
            int r = idx >> 5, u = idx & 31;
            int q = u >> 3, u8 = u & 7;
            uint32_t dst = sb + V_B + (uint32_t)q * 8192u +
                           sw128((uint32_t)r * 128u + (uint32_t)u8 * 16u);
            CP_ASYNC16(dst, wt4 + (size_t)(nc * 64 + r) * 32 + u);
        }
        CP_COMMIT();
    };

    loadWu(0);
    CP_WAIT0();
    __syncthreads();

    const int wm = (wid & 3) * 32, wn = (wid >> 2) * 32;
    const float2* x2  = (const float2*)x;
    const float2* bu2 = (const float2*)bup;
    float2* o2 = (float2*)out;

#pragma unroll 1
    for (int nc = 0; nc < 16; nc++) {
        Frag32 f2;
#pragma unroll
        for (int mt = 0; mt < 2; mt++)
#pragma unroll
            for (int nt = 0; nt < 4; nt++)
#pragma unroll
                for (int j = 0; j < 4; j++) f2.a[mt][nt][j] = 0.f;

#pragma unroll
        for (int q = 0; q < 4; q++)
            tile_compute32(sb + V_A + (uint32_t)q * 16384u,
                           sb + V_B + (uint32_t)q * 8192u, lid, wm, wn, f2);

        __syncthreads();                  // Wu reads done; buffer reusable
        if (nc + 1 < 16) loadWu(nc + 1);  // overlap next load with epilogue

        // epilogue: + bias + residual -> out (DRAM traffic spread per-chunk)
#pragma unroll
        for (int mt = 0; mt < 2; mt++)
#pragma unroll
            for (int nt = 0; nt < 4; nt++) {
                int col = nc * 64 + wn + nt * 8 + (lid & 3) * 2;
                int row = m0 + wm + mt * 16 + (lid >> 2);
                float2 bv = bu2[col >> 1];
                float* c = f2.a[mt][nt];
                float2 r0 = x2[(size_t)row * 512 + (col >> 1)];
                float2 r1 = x2[(size_t)(row + 8) * 512 + (col >> 1)];
                float2 o0, o1;
                o0.x = c[0] + bv.x + r0.x;  o0.y = c[1] + bv.y + r0.y;
                o1.x = c[2] + bv.x + r1.x;  o1.y = c[3] + bv.y + r1.y;
                o2[(size_t)row * 512 + (col >> 1)]       = o0;
                o2[(size_t)(row + 8) * 512 + (col >> 1)] = o1;
            }

        if (nc + 1 < 16) { CP_WAIT0(); __syncthreads(); }
    }
}

// ---------------- host launcher ----------------
extern "C" void kernel_launch(void* const* d_in, const int* in_sizes, int n_in,
                              void* d_out, int out_size) {
    const float* x   = (const float*)d_in[0];
    const float* lnw = (const float*)d_in[1];
    const float* lnb = (const float*)d_in[2];
    const float* wd  = (const float*)d_in[3];
    const float* bd  = (const float*)d_in[4];
    const float* wu  = (const float*)d_in[5];
    const float* bu  = (const float*)d_in[6];
    float* out = (float*)d_out;

    cudaFuncSetAttribute(g1_kernel, cudaFuncAttributeMaxDynamicSharedMemorySize,
                         G_SMEM);
    cudaFuncSetAttribute(g2_kernel, cudaFuncAttributeMaxDynamicSharedMemorySize,
                         V_SMEM);

    prep_t<<<512, 256>>>(wd, wu);
    ln_kernel<<<4096, 256>>>(x, lnw, lnb);
    g1_kernel<<<dim3(256, 2), 256, G_SMEM>>>(bd);
    g2_kernel<<<256, 256, V_SMEM>>>(x, bu, out);
    (void)in_sizes; (void)n_in; (void)out_size;
}